// round 10
// baseline (speedup 1.0000x reference)
#include <cuda_runtime.h>
#include <cstdint>

// Scatter-add message passing: out[dst] += x[src]
// x: [N, 64] fp32; edge_index: [2, E], int32 or int64 (detected on-device).
//
// R10 = R9 retry (two consecutive infra failures; source unchanged).
// Persistent grid-stride version of the R4/R8 winner:
//  - 16 lanes per group of 4 edges; lane c owns float4 chunk c.
//  - Grid = 8 CTAs/SM, each thread loops ~10 groups: amortizes CTA churn and
//    software-pipelines next iteration's loads under outstanding REDs.
//  - RED asm has NO memory clobber (fire-and-forget, no-return, dataflow
//    already orders gather->RED; kernel boundary flushes): this is what
//    permits the cross-iteration load hoisting.

__device__ int g_idx_is64;

__global__ void k_zero_detect(float4* __restrict__ out, int n4,
                              const int* __restrict__ ei_raw) {
    int i = blockIdx.x * blockDim.x + threadIdx.x;
    if (i < n4) out[i] = make_float4(0.f, 0.f, 0.f, 0.f);
    if (i == 0) {
        // values < 50000 => int64 layout has all-zero hi words
        int all_hi_zero = 1;
        #pragma unroll
        for (int j = 0; j < 64; j++)
            if (ei_raw[2 * j + 1] != 0) { all_hi_zero = 0; break; }
        g_idx_is64 = all_hi_zero;
    }
}

// No "memory" clobber: lets the compiler hoist the next iteration's loads
// above these fire-and-forget reductions. volatile keeps them alive/ordered
// among themselves.
__device__ __forceinline__ void red_v4(float* out, int dst, int c, float4 v) {
    float4* op = (float4*)(out + (size_t)dst * 64) + c;
    asm volatile("red.global.add.v4.f32 [%0], {%1, %2, %3, %4};"
                 :: "l"(op), "f"(v.x), "f"(v.y), "f"(v.z), "f"(v.w));
}

__global__ void __launch_bounds__(256, 8)
mp_scatter_persist(const float* __restrict__ x,
                   const void* __restrict__ ei_raw,
                   float* __restrict__ out,
                   int E, int G) {
    int c = threadIdx.x & 15;                 // float4 chunk within the row
    int g0 = (blockIdx.x * blockDim.x + threadIdx.x) >> 4;
    int gs = (gridDim.x * blockDim.x) >> 4;   // groups per pass

    bool is64 = (g_idx_is64 != 0);

    for (int g = g0; g < G; g += gs) {
        int e0 = g << 2;
        int n = min(4, E - e0);               // tail-safe

        int dst[4], src[4];
        if (is64) {
            const long long* ei = (const long long*)ei_raw;
            #pragma unroll
            for (int k = 0; k < 4; k++) {
                int e = e0 + ((k < n) ? k : 0);
                dst[k] = (int)__ldg(ei + e);
                src[k] = (int)__ldg(ei + E + e);
            }
        } else {
            const int* ei = (const int*)ei_raw;
            if (n == 4) {                     // aligned: e0 % 4 == 0
                int4 d4 = __ldg((const int4*)(ei + e0));
                int4 s4 = __ldg((const int4*)(ei + E + e0));
                dst[0] = d4.x; dst[1] = d4.y; dst[2] = d4.z; dst[3] = d4.w;
                src[0] = s4.x; src[1] = s4.y; src[2] = s4.z; src[3] = s4.w;
            } else {
                #pragma unroll
                for (int k = 0; k < 4; k++) {
                    int e = e0 + ((k < n) ? k : 0);
                    dst[k] = __ldg(ei + e);
                    src[k] = __ldg(ei + E + e);
                }
            }
        }

        // All 4 gathers in flight before any RED.
        float4 v[4];
        #pragma unroll
        for (int k = 0; k < 4; k++)
            v[k] = __ldg((const float4*)(x + (size_t)src[k] * 64) + c);

        #pragma unroll
        for (int k = 0; k < 4; k++)
            if (k < n) red_v4(out, dst[k], c, v[k]);
    }
}

extern "C" void kernel_launch(void* const* d_in, const int* in_sizes, int n_in,
                              void* d_out, int out_size) {
    const float* x = (const float*)d_in[0];
    const void* ei = d_in[1];
    float* out = (float*)d_out;

    int E = in_sizes[1] / 2;            // edge_index is [2, E]
    int G = (E + 3) / 4;                // groups of 4 edges

    int n4 = out_size / 4;              // float4 count of out
    int tb = 256;
    k_zero_detect<<<(n4 + tb - 1) / tb, tb>>>((float4*)out, n4,
                                              (const int*)ei);

    int blocks = 148 * 8;               // persistent: 8 CTAs per SM
    mp_scatter_persist<<<blocks, tb>>>(x, ei, out, E, G);
}

// round 11
// speedup vs baseline: 1.0395x; 1.0395x over previous
#include <cuda_runtime.h>
#include <cstdint>

// Scatter-add message passing: out[dst] += x[src]
// x: [N, 64] fp32; edge_index: [2, E], int32 or int64 (detected in-kernel).
//
// R11: R8 winning scatter body (MLP=4, 16 lanes/edge-quad, full occupancy;
// persistent variant regressed in R10 and is abandoned). Wrapper slimmed:
//  - dtype detect moved INTO the scatter kernel (8 broadcast loads of odd
//    int32 slots; int64 layout => all zero; P[false positive] ~ 50000^-8).
//  - zeroing via cudaMemsetAsync (driver memset node, no kernel launch).
//  - gathers use ld.global.cg (x has ~2% L1 hit rate; skip L1 allocation).

__device__ __forceinline__ void red_v4(float* out, int dst, int c, float4 v) {
    float4* op = (float4*)(out + (size_t)dst * 64) + c;
    asm volatile("red.global.add.v4.f32 [%0], {%1, %2, %3, %4};"
                 :: "l"(op), "f"(v.x), "f"(v.y), "f"(v.z), "f"(v.w)
                 : "memory");
}

__device__ __forceinline__ float4 ldcg_f4(const float4* p) {
    float4 v;
    asm volatile("ld.global.cg.v4.f32 {%0, %1, %2, %3}, [%4];"
                 : "=f"(v.x), "=f"(v.y), "=f"(v.z), "=f"(v.w) : "l"(p));
    return v;
}

__global__ void __launch_bounds__(256, 8)
mp_scatter4_kernel(const float* __restrict__ x,
                   const void* __restrict__ ei_raw,
                   float* __restrict__ out,
                   int E, int G) {
    int tid = blockIdx.x * blockDim.x + threadIdx.x;
    int g = tid >> 4;           // group of 4 consecutive edges
    int c = tid & 15;           // float4 chunk within the 64-float row
    if (g >= G) return;

    // In-kernel dtype detect: values < 50000, so an int64 layout has zero hi
    // words at odd int32 slots. 8 broadcast same-address loads, uniform
    // predicate -> no divergence, L1-resident after the first warp.
    const int* ei32 = (const int*)ei_raw;
    int hi_or = 0;
    #pragma unroll
    for (int j = 0; j < 8; j++) hi_or |= __ldg(ei32 + 2 * j + 1);
    bool is64 = (hi_or == 0);

    int e0 = g << 2;
    int n = min(4, E - e0);     // edges in this group (tail-safe)

    int dst[4], src[4];
    if (is64) {
        const long long* ei = (const long long*)ei_raw;
        #pragma unroll
        for (int k = 0; k < 4; k++) {
            int e = e0 + ((k < n) ? k : 0);
            dst[k] = (int)__ldg(ei + e);
            src[k] = (int)__ldg(ei + E + e);
        }
    } else {
        if (n == 4) {           // aligned: e0 % 4 == 0
            int4 d4 = __ldg((const int4*)(ei32 + e0));
            int4 s4 = __ldg((const int4*)(ei32 + E + e0));
            dst[0] = d4.x; dst[1] = d4.y; dst[2] = d4.z; dst[3] = d4.w;
            src[0] = s4.x; src[1] = s4.y; src[2] = s4.z; src[3] = s4.w;
        } else {
            #pragma unroll
            for (int k = 0; k < 4; k++) {
                int e = e0 + ((k < n) ? k : 0);
                dst[k] = __ldg(ei32 + e);
                src[k] = __ldg(ei32 + E + e);
            }
        }
    }

    // Phase 2: all 4 gathers in flight before any RED.
    float4 v[4];
    #pragma unroll
    for (int k = 0; k < 4; k++)
        v[k] = ldcg_f4((const float4*)(x + (size_t)src[k] * 64) + c);

    // Phase 3: fire-and-forget reductions.
    #pragma unroll
    for (int k = 0; k < 4; k++)
        if (k < n) red_v4(out, dst[k], c, v[k]);
}

extern "C" void kernel_launch(void* const* d_in, const int* in_sizes, int n_in,
                              void* d_out, int out_size) {
    const float* x = (const float*)d_in[0];
    const void* ei = d_in[1];
    float* out = (float*)d_out;

    int E = in_sizes[1] / 2;            // edge_index is [2, E]
    int G = (E + 3) / 4;                // groups of 4 edges

    cudaMemsetAsync(d_out, 0, (size_t)out_size * sizeof(float), 0);

    long long total = (long long)G * 16;
    int tb = 256;
    int blocks = (int)((total + tb - 1) / tb);
    mp_scatter4_kernel<<<blocks, tb>>>(x, ei, out, E, G);
}